// round 13
// baseline (speedup 1.0000x reference)
#include <cuda_runtime.h>
#include <cuda_fp16.h>
#include <math.h>

#define N 8192
#define M 8192
#define D 64
#define NIT 20

typedef unsigned long long ull;
typedef unsigned int uint;

static constexpr float EPS   = 0.05f;
static constexpr float ALPHA = 1.4426950408889634f;   // log2(e)
static constexpr float LN2   = 0.6931471805599453f;
static constexpr float KC    = (2.0f / 0.05f) * 1.4426950408889634f; // 57.7

// ---------------- scratch (device globals) ----------------
__device__ unsigned char dA8 [N * M];  // round(t/32)+128, t = KC*dot  (64 MB)
__device__ unsigned char dAT8[N * M];  // transpose                    (64 MB)
__device__ float  d_vt[N];             // potentials f32 (t units)
__device__ float  d_wt[M];
__device__ __half d_vtp[N];            // v/32 - 1152 (fp16 phase-1 operand)
__device__ __half d_wtp[M];
__device__ float  d_la[N];
__device__ float  d_lb[M];
__device__ float  d_x2[N];
__device__ float  d_y2[M];
__device__ float  d_an[N];
__device__ float  d_bn[M];

// ---------------- helpers ----------------
__device__ __forceinline__ float ex2(float x) {
    float r; asm("ex2.approx.f32 %0, %1;" : "=f"(r) : "f"(x)); return r;
}
__device__ __forceinline__ __half2 h2bits(uint u) {
    __half2 h; asm("mov.b32 %0, %1;" : "=r"(*(uint*)&h) : "r"(u)); return h;
}
__device__ __forceinline__ void fma2(ull& d, ull a, ull b) {
    asm("fma.rn.f32x2 %0, %1, %2, %0;" : "+l"(d) : "l"(a), "l"(b));
}
__device__ __forceinline__ ull bcast2(float a) {
    ull p; asm("mov.b64 %0, {%1, %1};" : "=l"(p) : "f"(a)); return p;
}
__device__ __forceinline__ void unpack2(ull p, float& lo, float& hi) {
    asm("mov.b64 {%0, %1}, %2;" : "=f"(lo), "=f"(hi) : "l"(p));
}
__device__ __forceinline__ ull pack2(float lo, float hi) {
    ull p; asm("mov.b64 %0, {%1, %2};" : "=l"(p) : "f"(lo), "f"(hi)); return p;
}
__device__ __forceinline__ uint qbyte(float v) {       // round(t/32)+128
    float f = fminf(fmaxf(v * 0.03125f, -127.f), 127.f);
    return (uint)(__float2int_rn(f) + 128);
}

// ---------------- GEMM: 128x128 tile, 8x8/thread, emit A8 + AT8 only -------
__global__ void __launch_bounds__(256) gemm_kernel(const float* __restrict__ X,
                                                   const float* __restrict__ Y) {
    __shared__ __align__(16) char sbuf[33792];
    float* sxT = (float*)sbuf;                 // [32][132]
    float* syT = sxT + 32 * 132;               // [32][132]
    unsigned char* ts = (unsigned char*)sbuf;  // [128][144] bytes

    int t  = threadIdx.x;
    int tx = t & 15, ty = t >> 4;
    int i0 = blockIdx.y * 128;
    int j0 = blockIdx.x * 128;

    ull acc[8][4];
    #pragma unroll
    for (int u = 0; u < 8; u++)
        #pragma unroll
        for (int v = 0; v < 4; v++) acc[u][v] = 0ull;

    #pragma unroll
    for (int k0 = 0; k0 < 64; k0 += 32) {
        if (k0) __syncthreads();
        #pragma unroll
        for (int it = 0; it < 4; it++) {
            int q = t + 256 * it;
            int r = q >> 3, c = q & 7;
            float4 fx = *reinterpret_cast<const float4*>(X + (size_t)(i0 + r) * D + k0 + c * 4);
            sxT[(c * 4 + 0) * 132 + r] = fx.x;
            sxT[(c * 4 + 1) * 132 + r] = fx.y;
            sxT[(c * 4 + 2) * 132 + r] = fx.z;
            sxT[(c * 4 + 3) * 132 + r] = fx.w;
            float4 fy = *reinterpret_cast<const float4*>(Y + (size_t)(j0 + r) * D + k0 + c * 4);
            syT[(c * 4 + 0) * 132 + r] = fy.x;
            syT[(c * 4 + 1) * 132 + r] = fy.y;
            syT[(c * 4 + 2) * 132 + r] = fy.z;
            syT[(c * 4 + 3) * 132 + r] = fy.w;
        }
        __syncthreads();

        #pragma unroll 8
        for (int k = 0; k < 32; k++) {
            float4 a0 = *reinterpret_cast<const float4*>(&sxT[k * 132 + ty * 8]);
            float4 a1 = *reinterpret_cast<const float4*>(&sxT[k * 132 + ty * 8 + 4]);
            float4 b0 = *reinterpret_cast<const float4*>(&syT[k * 132 + tx * 8]);
            float4 b1 = *reinterpret_cast<const float4*>(&syT[k * 132 + tx * 8 + 4]);
            ull bb0 = pack2(b0.x, b0.y), bb1 = pack2(b0.z, b0.w);
            ull bb2 = pack2(b1.x, b1.y), bb3 = pack2(b1.z, b1.w);
            float av[8] = {a0.x, a0.y, a0.z, a0.w, a1.x, a1.y, a1.z, a1.w};
            #pragma unroll
            for (int u = 0; u < 8; u++) {
                ull au = bcast2(av[u]);
                fma2(acc[u][0], au, bb0);
                fma2(acc[u][1], au, bb1);
                fma2(acc[u][2], au, bb2);
                fma2(acc[u][3], au, bb3);
            }
        }
    }

    __syncthreads();   // smem reads done; sbuf becomes ts

    #pragma unroll
    for (int u = 0; u < 8; u++) {
        float v[8];
        #pragma unroll
        for (int p = 0; p < 4; p++) {
            float lo, hi; unpack2(acc[u][p], lo, hi);
            v[2 * p] = lo * KC; v[2 * p + 1] = hi * KC;
        }
        uint qb[8];
        #pragma unroll
        for (int e = 0; e < 8; e++) qb[e] = qbyte(v[e]);
        uint2 pb;
        pb.x = qb[0] | (qb[1] << 8) | (qb[2] << 16) | (qb[3] << 24);
        pb.y = qb[4] | (qb[5] << 8) | (qb[6] << 16) | (qb[7] << 24);
        *reinterpret_cast<uint2*>(dA8 + (size_t)(i0 + ty * 8 + u) * M + j0 + tx * 8) = pb;
        #pragma unroll
        for (int e = 0; e < 8; e++)
            ts[(tx * 8 + e) * 144 + ty * 8 + u] = (unsigned char)qb[e];
    }

    __syncthreads();
    #pragma unroll
    for (int it = 0; it < 4; it++) {
        int q  = t + 256 * it;
        int jj = q >> 3, c = q & 7;
        uint4 o = *reinterpret_cast<const uint4*>(&ts[jj * 144 + c * 16]);
        *reinterpret_cast<uint4*>(dAT8 + (size_t)(j0 + jj) * N + i0 + c * 16) = o;
    }
}

// ---------------- row squared norms ----------------
__global__ void k_sqnorm(const float* __restrict__ X, const float* __restrict__ Y) {
    int w    = (blockIdx.x * blockDim.x + threadIdx.x) >> 5;
    int lane = threadIdx.x & 31;
    if (w >= N + M) return;
    const float* src = (w < N) ? (X + (size_t)w * D) : (Y + (size_t)(w - N) * D);
    float v0 = src[lane], v1 = src[lane + 32];
    float s = v0 * v0 + v1 * v1;
    #pragma unroll
    for (int off = 16; off; off >>= 1) s += __shfl_xor_sync(0xffffffffu, s, off);
    if (lane == 0) { if (w < N) d_x2[w] = s; else d_y2[w - N] = s; }
}

// ---------------- setup: sums + init (single block) ----------------
__global__ void k_setup(const float* __restrict__ a, const float* __restrict__ b) {
    __shared__ float sa[1024], sb[1024];
    int t = threadIdx.x;
    float s1 = 0.f, s2 = 0.f;
    for (int i = t; i < N; i += 1024) { s1 += a[i]; s2 += b[i]; }
    sa[t] = s1; sb[t] = s2; __syncthreads();
    for (int off = 512; off; off >>= 1) {
        if (t < off) { sa[t] += sa[t + off]; sb[t] += sb[t + off]; }
        __syncthreads();
    }
    float Sa = sa[0], Sb = sb[0];
    float lsa = logf(Sa), lsb = logf(Sb);
    for (int i = t; i < N; i += 1024) {
        float ai = a[i];
        d_la[i] = ALPHA * (logf(ai) - lsa);
        d_an[i] = ai / Sa;
        float bi = b[i];
        float lb = ALPHA * (logf(bi) - lsb);
        d_lb[i] = lb;
        d_bn[i] = bi / Sb;
        float w0 = lb - (ALPHA / EPS) * d_y2[i];   // g0 = 0
        d_wt[i]  = w0;
        d_wtp[i] = __float2half_rn(w0 * 0.03125f - 1152.f);
    }
}

// ---------------- two-phase LSE pass: warp/row, chunk-granular fix-up ------
// Phase 1: int8 stream + fp16 w' smem; per-CHUNK (16 elem) maxima in regs.
// Phase 2: only hot chunks (max >= rm-4 est units, ~2-3 per row) re-read;
//          truly hot elements get exact fp32: t = KC*dot(P[row],Q[e]) + w32[e].
template <bool ROWPASS>
__global__ void __launch_bounds__(256) pass_kernel(const float* __restrict__ P,
                                                   const float* __restrict__ Q) {
    __shared__ __align__(16) __half swp[8192];   // 16 KB: w' fp16
    const unsigned char* __restrict__ Mat8 = ROWPASS ? dA8   : dAT8;
    const __half* __restrict__ wpr  = ROWPASS ? d_wtp : d_vtp;
    const float*  __restrict__ w32  = ROWPASS ? d_wt  : d_vt;
    const float*  __restrict__ lvec = ROWPASS ? d_la  : d_lb;
    float*  __restrict__ vout  = ROWPASS ? d_vt  : d_wt;
    __half* __restrict__ voutp = ROWPASS ? d_vtp : d_wtp;

    int t = threadIdx.x;
    {
        const uint4* src = reinterpret_cast<const uint4*>(wpr);
        uint4* dst = reinterpret_cast<uint4*>(swp);
        #pragma unroll
        for (int it = 0; it < 4; it++) dst[t + 256 * it] = src[t + 256 * it];
    }
    __syncthreads();

    int warp = t >> 5, lane = t & 31;
    int row  = blockIdx.x * 8 + warp;
    const uint4* rp  = reinterpret_cast<const uint4*>(Mat8 + (size_t)row * M);
    const uint4* sw4 = reinterpret_cast<const uint4*>(swp);

    // ---- phase 1: 16 chunks/lane (16 int8 each), per-chunk maxima ----
    __half2 cmax[16];
    uint4 cur = rp[lane];
    #pragma unroll
    for (int c = 0; c < 16; c++) {
        uint4 nxt = cur;
        if (c < 15) nxt = rp[(c + 1) * 32 + lane];
        int wi = (c * 32 + lane) * 2;
        uint4 wa = sw4[wi], wb = sw4[wi + 1];
        const __half2* ha = (const __half2*)&wa;
        const __half2* hb = (const __half2*)&wb;
        __half2 e0 = __hadd2(h2bits(__byte_perm(cur.x, 0x00640064u, 0x4140)), ha[0]);
        __half2 e1 = __hadd2(h2bits(__byte_perm(cur.x, 0x00640064u, 0x4342)), ha[1]);
        __half2 e2 = __hadd2(h2bits(__byte_perm(cur.y, 0x00640064u, 0x4140)), ha[2]);
        __half2 e3 = __hadd2(h2bits(__byte_perm(cur.y, 0x00640064u, 0x4342)), ha[3]);
        __half2 e4 = __hadd2(h2bits(__byte_perm(cur.z, 0x00640064u, 0x4140)), hb[0]);
        __half2 e5 = __hadd2(h2bits(__byte_perm(cur.z, 0x00640064u, 0x4342)), hb[1]);
        __half2 e6 = __hadd2(h2bits(__byte_perm(cur.w, 0x00640064u, 0x4140)), hb[2]);
        __half2 e7 = __hadd2(h2bits(__byte_perm(cur.w, 0x00640064u, 0x4342)), hb[3]);
        cmax[c] = __hmax2(__hmax2(__hmax2(e0, e1), __hmax2(e2, e3)),
                          __hmax2(__hmax2(e4, e5), __hmax2(e6, e7)));
        cur = nxt;
    }

    // warp-wide approximate row max (units of t/32)
    __half2 gAll = cmax[0];
    #pragma unroll
    for (int c = 1; c < 16; c++) gAll = __hmax2(gAll, cmax[c]);
    float rm = fmaxf(__low2float(gAll), __high2float(gAll));
    #pragma unroll
    for (int off = 16; off; off >>= 1)
        rm = fmaxf(rm, __shfl_xor_sync(0xffffffffu, rm, off));

    float thr = rm - 4.0f;          // est err <= ~1.1/side + 40/32 significance
    float m2  = 32.f * rm + 40.f;   // >= true max (t units)

    const float4* pv = reinterpret_cast<const float4*>(P + (size_t)row * D);

    // ---- phase 2: exact fp32 fix-up, CHUNK granularity ----
    float s = 0.f;
    #pragma unroll 1
    for (int c = 0; c < 16; c++) {
        float cf = fmaxf(__low2float(cmax[c]), __high2float(cmax[c]));
        bool hot = cf >= thr;
        if (__ballot_sync(0xffffffffu, hot) == 0) continue;
        if (hot) {
            uint4 pk = rp[c * 32 + lane];        // L1/L2 hit
            int wi = (c * 32 + lane) * 2;
            uint4 wa = sw4[wi], wb = sw4[wi + 1];
            const __half2* ha = (const __half2*)&wa;
            const __half2* hb = (const __half2*)&wb;
            uint words[4] = {pk.x, pk.y, pk.z, pk.w};
            int eb = (c * 32 + lane) * 16;
            #pragma unroll 1
            for (int q = 0; q < 4; q++) {
                __half2 w2a = (q < 2) ? ha[2 * q]     : hb[2 * (q - 2)];
                __half2 w2b = (q < 2) ? ha[2 * q + 1] : hb[2 * (q - 2) + 1];
                __half2 ea = __hadd2(h2bits(__byte_perm(words[q], 0x00640064u, 0x4140)), w2a);
                __half2 eb2 = __hadd2(h2bits(__byte_perm(words[q], 0x00640064u, 0x4342)), w2b);
                float ef[4] = {__low2float(ea),  __high2float(ea),
                               __low2float(eb2), __high2float(eb2)};
                #pragma unroll 1
                for (int z = 0; z < 4; z++) {
                    if (ef[z] >= thr) {
                        int e = eb + q * 4 + z;
                        const float4* qv = reinterpret_cast<const float4*>(Q + (size_t)e * D);
                        float dot = 0.f;
                        #pragma unroll
                        for (int kk = 0; kk < 16; kk++) {
                            float4 av = __ldg(&pv[kk]);
                            float4 bv = __ldg(&qv[kk]);
                            dot += av.x * bv.x + av.y * bv.y
                                 + av.z * bv.z + av.w * bv.w;
                        }
                        s += ex2(fmaf(KC, dot, __ldg(&w32[e])) - m2);
                    }
                }
            }
        }
    }
    #pragma unroll
    for (int off = 16; off; off >>= 1)
        s += __shfl_xor_sync(0xffffffffu, s, off);
    if (lane == 0) {
        float r = lvec[row] - (m2 + log2f(s));
        vout[row]  = r;
        voutp[row] = __float2half_rn(r * 0.03125f - 1152.f);
    }
}

// ---------------- final reduction ----------------
__global__ void k_final(float* __restrict__ out) {
    __shared__ float sm[1024];
    int t = threadIdx.x;
    float s = 0.f;
    for (int i = t; i < N; i += 1024)
        s += d_an[i] * (d_x2[i] + EPS * LN2 * (d_vt[i] - d_la[i]));
    for (int j = t; j < M; j += 1024)
        s += d_bn[j] * (d_y2[j] + EPS * LN2 * (d_wt[j] - d_lb[j]));
    sm[t] = s; __syncthreads();
    for (int off = 512; off; off >>= 1) {
        if (t < off) sm[t] += sm[t + off];
        __syncthreads();
    }
    if (t == 0) out[0] = sm[0];
}

// ---------------- launch (pass is 4th launch -> ncu captures it) -----------
extern "C" void kernel_launch(void* const* d_in, const int* in_sizes, int n_in,
                              void* d_out, int out_size) {
    const float* a = (const float*)d_in[0];
    const float* x = (const float*)d_in[1];
    const float* b = (const float*)d_in[2];
    const float* y = (const float*)d_in[3];
    float* out = (float*)d_out;

    gemm_kernel<<<dim3(M / 128, N / 128), 256>>>(x, y);   // launch 1
    k_sqnorm<<<(N + M) / 8, 256>>>(x, y);                 // launch 2
    k_setup<<<1, 1024>>>(a, b);                           // launch 3

    for (int it = 0; it < NIT; ++it) {
        pass_kernel<true ><<<N / 8, 256>>>(x, y);  // launch 4 <- ncu capture
        pass_kernel<false><<<M / 8, 256>>>(y, x);
    }
    pass_kernel<true><<<N / 8, 256>>>(x, y);       // f_fin; g_fin == g_20
    k_final<<<1, 1024>>>(out);
}

// round 14
// speedup vs baseline: 4.3430x; 4.3430x over previous
#include <cuda_runtime.h>
#include <math.h>

#define N 8192
#define M 8192
#define D 64
#define NIT 20

typedef unsigned long long ull;
typedef unsigned int uint;

static constexpr float EPS   = 0.05f;
static constexpr float ALPHA = 1.4426950408889634f;   // log2(e)
static constexpr float LN2   = 0.6931471805599453f;
static constexpr float KC    = (2.0f / 0.05f) * 1.4426950408889634f; // 57.7
static constexpr float QSI   = 0.125f;      // dequant step
static constexpr float QSF   = 8.0f * KC;   // quant scale applied to raw dot

// ---------------- scratch (device globals) ----------------
__device__ short dA [N * M];   // round(8*KC*(x@y^T)) row-major [i][j]
__device__ short dAT[N * M];   // transpose [j][i]
__device__ float d_vt[N];
__device__ float d_wt[M];
__device__ float d_la[N];
__device__ float d_lb[M];
__device__ float d_x2[N];
__device__ float d_y2[M];
__device__ float d_an[N];
__device__ float d_bn[M];

// ---------------- helpers ----------------
__device__ __forceinline__ float ex2(float x) {        // MUFU.EX2
    float r; asm("ex2.approx.f32 %0, %1;" : "=f"(r) : "f"(x)); return r;
}
__device__ __forceinline__ void fma2(ull& d, ull a, ull b) {
    asm("fma.rn.f32x2 %0, %1, %2, %0;" : "+l"(d) : "l"(a), "l"(b));
}
__device__ __forceinline__ ull bcast2(float a) {
    ull p; asm("mov.b64 %0, {%1, %1};" : "=l"(p) : "f"(a)); return p;
}
__device__ __forceinline__ void unpack2(ull p, float& lo, float& hi) {
    asm("mov.b64 {%0, %1}, %2;" : "=f"(lo), "=f"(hi) : "l"(p));
}
__device__ __forceinline__ ull pack2(float lo, float hi) {
    ull p; asm("mov.b64 %0, {%1, %2};" : "=l"(p) : "f"(lo), "f"(hi)); return p;
}
__device__ __forceinline__ short quant(float s) {
    float v = fminf(fmaxf(s * QSF, -32600.f), 32600.f);
    return (short)__float2int_rn(v);
}

// ---------------- GEMM: 128x128 tile, 256 thr, 8x8/thread, k-chunk 32 -------
__global__ void __launch_bounds__(256) gemm_kernel(const float* __restrict__ X,
                                                   const float* __restrict__ Y) {
    __shared__ __align__(16) char sbuf[34816];
    float* sxT = (float*)sbuf;            // [32][132]
    float* syT = sxT + 32 * 132;          // [32][132]
    short* ts  = (short*)sbuf;            // [128][136]

    int t  = threadIdx.x;
    int tx = t & 15, ty = t >> 4;
    int i0 = blockIdx.y * 128;
    int j0 = blockIdx.x * 128;

    ull acc[8][4];
    #pragma unroll
    for (int u = 0; u < 8; u++)
        #pragma unroll
        for (int v = 0; v < 4; v++) acc[u][v] = 0ull;

    #pragma unroll
    for (int k0 = 0; k0 < 64; k0 += 32) {
        if (k0) __syncthreads();
        #pragma unroll
        for (int it = 0; it < 4; it++) {
            int q = t + 256 * it;
            int r = q >> 3, c = q & 7;
            float4 fx = *reinterpret_cast<const float4*>(X + (size_t)(i0 + r) * D + k0 + c * 4);
            sxT[(c * 4 + 0) * 132 + r] = fx.x;
            sxT[(c * 4 + 1) * 132 + r] = fx.y;
            sxT[(c * 4 + 2) * 132 + r] = fx.z;
            sxT[(c * 4 + 3) * 132 + r] = fx.w;
            float4 fy = *reinterpret_cast<const float4*>(Y + (size_t)(j0 + r) * D + k0 + c * 4);
            syT[(c * 4 + 0) * 132 + r] = fy.x;
            syT[(c * 4 + 1) * 132 + r] = fy.y;
            syT[(c * 4 + 2) * 132 + r] = fy.z;
            syT[(c * 4 + 3) * 132 + r] = fy.w;
        }
        __syncthreads();

        #pragma unroll 8
        for (int k = 0; k < 32; k++) {
            float4 a0 = *reinterpret_cast<const float4*>(&sxT[k * 132 + ty * 8]);
            float4 a1 = *reinterpret_cast<const float4*>(&sxT[k * 132 + ty * 8 + 4]);
            float4 b0 = *reinterpret_cast<const float4*>(&syT[k * 132 + tx * 8]);
            float4 b1 = *reinterpret_cast<const float4*>(&syT[k * 132 + tx * 8 + 4]);
            ull bb0 = pack2(b0.x, b0.y), bb1 = pack2(b0.z, b0.w);
            ull bb2 = pack2(b1.x, b1.y), bb3 = pack2(b1.z, b1.w);
            float av[8] = {a0.x, a0.y, a0.z, a0.w, a1.x, a1.y, a1.z, a1.w};
            #pragma unroll
            for (int u = 0; u < 8; u++) {
                ull au = bcast2(av[u]);
                fma2(acc[u][0], au, bb0);
                fma2(acc[u][1], au, bb1);
                fma2(acc[u][2], au, bb2);
                fma2(acc[u][3], au, bb3);
            }
        }
    }

    short q8[8][8];
    #pragma unroll
    for (int u = 0; u < 8; u++)
        #pragma unroll
        for (int v = 0; v < 4; v++) {
            float lo, hi; unpack2(acc[u][v], lo, hi);
            q8[u][2 * v] = quant(lo); q8[u][2 * v + 1] = quant(hi);
        }

    #pragma unroll
    for (int u = 0; u < 8; u++) {
        int4 o;
        o.x = (int)(unsigned short)q8[u][0] | ((int)q8[u][1] << 16);
        o.y = (int)(unsigned short)q8[u][2] | ((int)q8[u][3] << 16);
        o.z = (int)(unsigned short)q8[u][4] | ((int)q8[u][5] << 16);
        o.w = (int)(unsigned short)q8[u][6] | ((int)q8[u][7] << 16);
        *reinterpret_cast<int4*>(dA + (size_t)(i0 + ty * 8 + u) * M + j0 + tx * 8) = o;
    }

    __syncthreads();
    #pragma unroll
    for (int u = 0; u < 8; u++)
        #pragma unroll
        for (int v = 0; v < 8; v++)
            ts[(tx * 8 + v) * 136 + ty * 8 + u] = q8[u][v];
    __syncthreads();
    #pragma unroll
    for (int it = 0; it < 8; it++) {
        int q = t + 256 * it;
        int jj = q >> 4, c = q & 15;
        int4 o = *reinterpret_cast<const int4*>(&ts[jj * 136 + c * 8]);
        *reinterpret_cast<int4*>(dAT + (size_t)(j0 + jj) * N + i0 + c * 8) = o;
    }
}

// ---------------- row squared norms ----------------
__global__ void k_sqnorm(const float* __restrict__ X, const float* __restrict__ Y) {
    int w    = (blockIdx.x * blockDim.x + threadIdx.x) >> 5;
    int lane = threadIdx.x & 31;
    if (w >= N + M) return;
    const float* src = (w < N) ? (X + (size_t)w * D) : (Y + (size_t)(w - N) * D);
    float v0 = src[lane], v1 = src[lane + 32];
    float s = v0 * v0 + v1 * v1;
    #pragma unroll
    for (int off = 16; off; off >>= 1) s += __shfl_xor_sync(0xffffffffu, s, off);
    if (lane == 0) { if (w < N) d_x2[w] = s; else d_y2[w - N] = s; }
}

// ---------------- setup: sums + init (single block) ----------------
__global__ void k_setup(const float* __restrict__ a, const float* __restrict__ b) {
    __shared__ float sa[1024], sb[1024];
    int t = threadIdx.x;
    float s1 = 0.f, s2 = 0.f;
    for (int i = t; i < N; i += 1024) { s1 += a[i]; s2 += b[i]; }
    sa[t] = s1; sb[t] = s2; __syncthreads();
    for (int off = 512; off; off >>= 1) {
        if (t < off) { sa[t] += sa[t + off]; sb[t] += sb[t + off]; }
        __syncthreads();
    }
    float Sa = sa[0], Sb = sb[0];
    float lsa = logf(Sa), lsb = logf(Sb);
    for (int i = t; i < N; i += 1024) {
        float ai = a[i];
        d_la[i] = ALPHA * (logf(ai) - lsa);
        d_an[i] = ai / Sa;
        float bi = b[i];
        float lb = ALPHA * (logf(bi) - lsb);
        d_lb[i] = lb;
        d_bn[i] = bi / Sb;
        d_wt[i] = lb - (ALPHA / EPS) * d_y2[i];   // g0 = 0
    }
}

// ---------------- LSE pass: warp/row, w in smem, vote-skip (R4 proven) -----
// ROWPASS: v~_i = la_i - L2SE_j( 0.125*A[i][j] + w~_j )
// Prefetch depth 4 (was 8): regs <=64 -> 4 blocks/SM -> occ 50%.
template <bool ROWPASS>
__global__ void __launch_bounds__(256) pass_kernel() {
    __shared__ __align__(16) float sw[8192];
    const short* __restrict__ Mat  = ROWPASS ? dA  : dAT;
    const float* __restrict__ win  = ROWPASS ? d_wt : d_vt;
    const float* __restrict__ lvec = ROWPASS ? d_la : d_lb;
    float*       __restrict__ vout = ROWPASS ? d_vt : d_wt;

    int t = threadIdx.x;
    {
        const float4* wp = reinterpret_cast<const float4*>(win);
        float4* dst = reinterpret_cast<float4*>(sw);
        #pragma unroll
        for (int it = 0; it < 8; it++) dst[t + 256 * it] = wp[t + 256 * it];
    }
    __syncthreads();

    int warp = t >> 5, lane = t & 31;
    int row  = blockIdx.x * 8 + warp;
    const int4* rowp = reinterpret_cast<const int4*>(Mat + (size_t)row * M);

    float m = -INFINITY, s = 0.f;

    int4 pk[4];
    #pragma unroll
    for (int u = 0; u < 4; u++) pk[u] = rowp[u * 32 + lane];

    #pragma unroll
    for (int c0 = 0; c0 < 8; c0++) {
        int4 nk[4];
        if (c0 < 7) {
            #pragma unroll
            for (int u = 0; u < 4; u++) nk[u] = rowp[(c0 + 1) * 128 + u * 32 + lane];
        }
        #pragma unroll
        for (int u = 0; u < 4; u++) {
            int e = (c0 * 128 + u * 32 + lane) * 8;
            float4 wa = *reinterpret_cast<const float4*>(&sw[e]);
            float4 wb = *reinterpret_cast<const float4*>(&sw[e + 4]);
            float t0 = fmaf((float)(short)(pk[u].x), QSI, wa.x);
            float t1 = fmaf((float)(pk[u].x >> 16),  QSI, wa.y);
            float t2 = fmaf((float)(short)(pk[u].y), QSI, wa.z);
            float t3 = fmaf((float)(pk[u].y >> 16),  QSI, wa.w);
            float t4 = fmaf((float)(short)(pk[u].z), QSI, wb.x);
            float t5 = fmaf((float)(pk[u].z >> 16),  QSI, wb.y);
            float t6 = fmaf((float)(short)(pk[u].w), QSI, wb.z);
            float t7 = fmaf((float)(pk[u].w >> 16),  QSI, wb.w);
            float lm = fmaxf(fmaxf(fmaxf(t0, t1), fmaxf(t2, t3)),
                             fmaxf(fmaxf(t4, t5), fmaxf(t6, t7)));
            // warp-uniform skip: every skipped term < 2^-40 relative
            if (!__all_sync(0xffffffffu, lm < m - 40.f)) {
                float nm = fmaxf(m, lm);
                float r  = ex2(m - nm);
                float e8 = ((ex2(t0 - nm) + ex2(t1 - nm)) + (ex2(t2 - nm) + ex2(t3 - nm)))
                         + ((ex2(t4 - nm) + ex2(t5 - nm)) + (ex2(t6 - nm) + ex2(t7 - nm)));
                s = fmaf(s, r, e8);
                m = nm;
            }
        }
        if (c0 < 7) {
            #pragma unroll
            for (int u = 0; u < 4; u++) pk[u] = nk[u];
        }
    }

    #pragma unroll
    for (int off = 16; off; off >>= 1) {
        float m2 = __shfl_xor_sync(0xffffffffu, m, off);
        float s2 = __shfl_xor_sync(0xffffffffu, s, off);
        float nm = fmaxf(m, m2);
        s = s * ex2(m - nm) + s2 * ex2(m2 - nm);
        m = nm;
    }
    if (lane == 0) vout[row] = lvec[row] - (m + log2f(s));
}

// ---------------- final reduction ----------------
__global__ void k_final(float* __restrict__ out) {
    __shared__ float sm[1024];
    int t = threadIdx.x;
    float s = 0.f;
    for (int i = t; i < N; i += 1024)
        s += d_an[i] * (d_x2[i] + EPS * LN2 * (d_vt[i] - d_la[i]));
    for (int j = t; j < M; j += 1024)
        s += d_bn[j] * (d_y2[j] + EPS * LN2 * (d_wt[j] - d_lb[j]));
    sm[t] = s; __syncthreads();
    for (int off = 512; off; off >>= 1) {
        if (t < off) sm[t] += sm[t + off];
        __syncthreads();
    }
    if (t == 0) out[0] = sm[0];
}

// ---------------- launch (pass is 4th launch -> ncu captures it) -----------
extern "C" void kernel_launch(void* const* d_in, const int* in_sizes, int n_in,
                              void* d_out, int out_size) {
    const float* a = (const float*)d_in[0];
    const float* x = (const float*)d_in[1];
    const float* b = (const float*)d_in[2];
    const float* y = (const float*)d_in[3];
    float* out = (float*)d_out;

    gemm_kernel<<<dim3(M / 128, N / 128), 256>>>(x, y);   // launch 1
    k_sqnorm<<<(N + M) / 8, 256>>>(x, y);                 // launch 2
    k_setup<<<1, 1024>>>(a, b);                           // launch 3

    for (int it = 0; it < NIT; ++it) {
        pass_kernel<true ><<<N / 8, 256>>>();  // launch 4 <- ncu capture
        pass_kernel<false><<<M / 8, 256>>>();
    }
    pass_kernel<true><<<N / 8, 256>>>();       // f_fin; g_fin == g_20
    k_final<<<1, 1024>>>(out);
}